// round 10
// baseline (speedup 1.0000x reference)
#include <cuda_runtime.h>
#include <cuda_bf16.h>
#include <cstdint>

// Batched inverse of 3x3 upper-triangular matrices, rows of 9 fp32.
//   in : [a b c | . d e | . . f]
//   out: [1/a  -b/(ad)  (be-cd)/(adf) | 0  1/d  -e/(df) | 0 0 1/f]
//
// HBM-stream-bound at ~7.15 TB/s effective (89% of spec); all structural
// levers (pipeline/bulk-TMA/bursts/warp-autonomy/cache policy/MUFU) have
// been individually ruled out, bench noise is +-1us. R10 sweeps the last
// launch-shape parameter: CTA granularity. 128-thread / 128-row CTAs,
// 4.6KB smem -> 16 CTAs/SM (still 64 warps): barrier convoys shrink from
// 8 warps to 4, and 16 independent CTAs per SM decorrelate load/store
// phases more finely. Everything else identical to the best kernel (R5).
//
// Coalescing: LDG.128/STG.128 block-contiguous, evict-first hints.
// Smem banks: staging = consecutive float4 (conflict-free); compute
// addresses word 9t+k, gcd(9,32)=1 -> all 32 lanes distinct banks.
// Math: ONE reciprocal per row: ip = rcp(a*d*f);
//   1/a=(d*f)ip  1/d=(a*f)ip  1/f=(a*d)ip
//   o01=-(b*f)ip o12=-(e*a)ip o02=(b*e-c*d)ip
// Diagonal in [0.5,1.5) -> a*d*f in [0.125,3.4): safe; rel_err ~7e-8.

#define THREADS 128
#define ROWS_PER_BLOCK 128
#define FLOATS_PER_BLOCK (ROWS_PER_BLOCK * 9)   // 1152
#define VEC_PER_BLOCK (FLOATS_PER_BLOCK / 4)    // 288  (2.25 per thread)

__device__ __forceinline__ void inv3_row(const float* __restrict__ p,
                                         float* __restrict__ q)
{
    float a = p[0], b = p[1], c = p[2];
    float d = p[4], e = p[5];
    float f = p[8];

    float ad = a * d;
    float df = d * f;
    float af = a * f;
    float ip = __frcp_rn(ad * f);      // single reciprocal: 1/(a d f)

    float ia  = df * ip;               // 1/a
    float id  = af * ip;               // 1/d
    float iff = ad * ip;               // 1/f
    float o01 = -(b * f) * ip;         // -b/(ad)
    float o12 = -(e * a) * ip;         // -e/(df)
    float o02 = (b * e - c * d) * ip;  // (be - cd)/(adf)

    q[0] = ia;
    q[1] = o01;
    q[2] = o02;
    q[3] = 0.0f;
    q[4] = id;
    q[5] = o12;
    q[6] = 0.0f;
    q[7] = 0.0f;
    q[8] = iff;
}

__global__ __launch_bounds__(THREADS, 16) void inv3_vec_kernel(
    const float4* __restrict__ in, float4* __restrict__ out)
{
    __shared__ float s[FLOATS_PER_BLOCK];  // 4608 B

    const long long base_vec = (long long)blockIdx.x * VEC_PER_BLOCK;
    float4* sv = reinterpret_cast<float4*>(s);

    // ---- Stage in: 288 float4, 2-3 per thread, coalesced, evict-first ----
#pragma unroll
    for (int i = 0; i < 3; i++) {
        int li = threadIdx.x + i * THREADS;
        if (li < VEC_PER_BLOCK)
            sv[li] = __ldcs(&in[base_vec + li]);
    }
    __syncthreads();

    // ---- Compute: 1 row per thread, in place in smem ----
    {
        float* p = &s[threadIdx.x * 9];
        inv3_row(p, p);
    }
    __syncthreads();

    // ---- Stage out: 288 float4, coalesced, streaming stores ----
#pragma unroll
    for (int i = 0; i < 3; i++) {
        int li = threadIdx.x + i * THREADS;
        if (li < VEC_PER_BLOCK)
            __stcs(&out[base_vec + li], sv[li]);
    }
}

// Scalar tail for rows not covered by full blocks (not hit for N=8388608).
__global__ void inv3_tail_kernel(const float* __restrict__ in,
                                 float* __restrict__ out, int nrows)
{
    int row = blockIdx.x * blockDim.x + threadIdx.x;
    if (row >= nrows) return;
    inv3_row(in + (long long)row * 9, out + (long long)row * 9);
}

extern "C" void kernel_launch(void* const* d_in, const int* in_sizes, int n_in,
                              void* d_out, int out_size)
{
    const float* x = (const float*)d_in[0];
    float* y = (float*)d_out;
    long long total_floats = in_sizes[0];
    long long nrows = total_floats / 9;

    long long nblocks = nrows / ROWS_PER_BLOCK;
    if (nblocks > 0) {
        inv3_vec_kernel<<<(unsigned)nblocks, THREADS>>>(
            (const float4*)x, (float4*)y);
    }
    long long done = nblocks * ROWS_PER_BLOCK;
    int rem = (int)(nrows - done);
    if (rem > 0) {
        inv3_tail_kernel<<<(rem + 127) / 128, 128>>>(
            x + done * 9, y + done * 9, rem);
    }
}